// round 1
// baseline (speedup 1.0000x reference)
#include <cuda_runtime.h>

// Problem constants
#define NN      512      // x / columns of A
#define MM      512      // b / rows of A
#define NB      32       // columns per SMEM block
#define NBLK    (NN / NB)
#define STRIDE  36       // padded row stride (floats): 16B-aligned, bank-conflict-free
#define TPB     512
#define C_ALPHA 0.005f
#define C_SCALE 0.001f
#define C_DELTA 0.1f
#define MAX_UPD 51       // MAX_ITER + 1 possible updates

__device__ __forceinline__ void cp_async16(float* dst_smem, const float* src_gmem) {
    unsigned d = (unsigned)__cvta_generic_to_shared(dst_smem);
    asm volatile("cp.async.cg.shared.global [%0], [%1], 16;" :: "r"(d), "l"(src_gmem));
}
__device__ __forceinline__ void cp_commit() { asm volatile("cp.async.commit_group;"); }
__device__ __forceinline__ void cp_wait0()  { asm volatile("cp.async.wait_group 0;"); }

extern __shared__ float smem[];

// Load column block j (512 rows x 32 cols) of A into sA with row stride 36.
__device__ __forceinline__ void load_block(float* sA, const float* __restrict__ Ap,
                                           int j, int tid) {
#pragma unroll
    for (int i = 0; i < 8; i++) {
        int lin = i * TPB + tid;      // 0..4095
        int r = lin >> 3;             // row 0..511
        int s = lin & 7;              // float4 segment 0..7
        cp_async16(sA + r * STRIDE + s * 4,
                   Ap + (size_t)r * NN + j * NB + s * 4);
    }
    cp_commit();
}

__global__ __launch_bounds__(TPB, 2)
void lva_kernel(const float* __restrict__ xin,
                const float* __restrict__ Ain,
                const float* __restrict__ bin,
                float* __restrict__ xout) {
    const int p   = blockIdx.x;
    const int tid = threadIdx.x;

    float* sA    = smem;                    // 512*36 = 18432 floats
    float* sx    = sA + NN * STRIDE;        // 512
    float* sy    = sx + NN;                 // 512
    float* sviol = sy + MM;                 // 512
    float* sb    = sviol + MM;              // 512
    float* spart = sb + MM;                 // 512 (g partials [16][32])
    float* sred  = spart + TPB;             // 32

    const float* Ap = Ain + (size_t)p * (MM * NN);

    sx[tid] = xin[p * NN + tid];
    sb[tid] = bin[p * MM + tid];
    sy[tid] = 0.0f;
    __syncthreads();

    // ---------- initial sweep: y = A @ x ----------
    for (int j = 0; j < NBLK; j++) {
        load_block(sA, Ap, j, tid);
        cp_wait0();
        __syncthreads();

        float acc = 0.0f;
        const float4* row = (const float4*)(sA + tid * STRIDE);
#pragma unroll
        for (int s = 0; s < 8; s++) {
            float4 a = row[s];
            int c = j * NB + s * 4;
            acc = fmaf(a.x, sx[c + 0], acc);
            acc = fmaf(a.y, sx[c + 1], acc);
            acc = fmaf(a.z, sx[c + 2], acc);
            acc = fmaf(a.w, sx[c + 3], acc);
        }
        sy[tid] += acc;
        __syncthreads();   // sA free for next block
    }

    // ---------- finalize: viol, total ----------
    float v = fmaxf(__fadd_rn(sy[tid], -sb[tid]), 0.0f);
    sviol[tid] = v;
#pragma unroll
    for (int o = 16; o > 0; o >>= 1) v += __shfl_down_sync(0xffffffffu, v, o);
    if ((tid & 31) == 0) sred[tid >> 5] = v;
    __syncthreads();
    if (tid < 32) {
        float w = (tid < 16) ? sred[tid] : 0.0f;
#pragma unroll
        for (int o = 8; o > 0; o >>= 1) w += __shfl_down_sync(0xffffffffu, w, o);
        if (tid == 0) sred[16] = w;
    }
    __syncthreads();
    float total = sred[16];

    // ---------- iterate: fused (g + x-update + next Ax) single sweep ----------
    int it = 0;
    while (it < MAX_UPD && total >= C_DELTA) {
        sy[tid] = 0.0f;   // owner-thread only, no barrier needed

        for (int j = 0; j < NBLK; j++) {
            load_block(sA, Ap, j, tid);
            cp_wait0();
            __syncthreads();

            // g pass: g_c = sum_m viol[m] * A[m, j*32+c]
            {
                int c = tid & 31, k = tid >> 5;
                const float* bp = sA + (k * 32) * STRIDE + c;
                const float* vp = sviol + k * 32;
                float g = 0.0f;
#pragma unroll
                for (int m = 0; m < 32; m++)
                    g = fmaf(vp[m], bp[m * STRIDE], g);
                spart[k * 32 + c] = g;
            }
            __syncthreads();

            // x update for this block's 32 columns (exact scalar formula)
            if (tid < 32) {
                float g = 0.0f;
#pragma unroll
                for (int k = 0; k < 16; k++) g += spart[k * 32 + tid];
                int col = j * NB + tid;
                float xo  = sx[col];
                float den = __fadd_rn(1.0f, __fmul_rn(C_SCALE, g));
                float lr  = __fdiv_rn(C_ALPHA, den);
                float xn  = __fsub_rn(xo, __fmul_rn(lr, g));
                sx[col]   = fmaxf(xn, 0.0f);
            }
            __syncthreads();

            // y pass: y_m += A[m, block] . x'[block]   (next iteration's Ax)
            {
                float acc = 0.0f;
                const float4* row = (const float4*)(sA + tid * STRIDE);
#pragma unroll
                for (int s = 0; s < 8; s++) {
                    float4 a = row[s];
                    int c = j * NB + s * 4;
                    acc = fmaf(a.x, sx[c + 0], acc);
                    acc = fmaf(a.y, sx[c + 1], acc);
                    acc = fmaf(a.z, sx[c + 2], acc);
                    acc = fmaf(a.w, sx[c + 3], acc);
                }
                sy[tid] += acc;
            }
            __syncthreads();   // sA free for next block
        }

        // finalize
        float vv = fmaxf(__fadd_rn(sy[tid], -sb[tid]), 0.0f);
        sviol[tid] = vv;
#pragma unroll
        for (int o = 16; o > 0; o >>= 1) vv += __shfl_down_sync(0xffffffffu, vv, o);
        if ((tid & 31) == 0) sred[tid >> 5] = vv;
        __syncthreads();
        if (tid < 32) {
            float w = (tid < 16) ? sred[tid] : 0.0f;
#pragma unroll
            for (int o = 8; o > 0; o >>= 1) w += __shfl_down_sync(0xffffffffu, w, o);
            if (tid == 0) sred[16] = w;
        }
        __syncthreads();
        total = sred[16];
        it++;
    }

    xout[p * NN + tid] = sx[tid];
}

extern "C" void kernel_launch(void* const* d_in, const int* in_sizes, int n_in,
                              void* d_out, int out_size) {
    // metadata order: x [B,S,N], A [B,S,M,N], b [B,S,M]
    const float* x = (const float*)d_in[0];
    const float* A = (const float*)d_in[1];
    const float* b = (const float*)d_in[2];
    float* out = (float*)d_out;

    // Defensive: A is the (only) large input.
    if (n_in == 3 && in_sizes[0] > in_sizes[1]) {
        A = (const float*)d_in[0];
        x = (const float*)d_in[1];
    }

    int nprob = out_size / NN;   // 256
    size_t smem_bytes = (size_t)(NN * STRIDE + NN + MM + MM + MM + TPB + 32) * sizeof(float);

    cudaFuncSetAttribute(lva_kernel, cudaFuncAttributeMaxDynamicSharedMemorySize,
                         (int)smem_bytes);
    lva_kernel<<<nprob, TPB, smem_bytes>>>(x, A, b, out);
}